// round 3
// baseline (speedup 1.0000x reference)
#include <cuda_runtime.h>
#include <cuda_bf16.h>
#include <math.h>

// Problem constants
#define BN     16384           // B*N tokens
#define DIM    512
#define NC     4096            // codes per stage
#define NQ     4               // stages
#define CBSZ   (NC * DIM)      // floats per stage codebook
#define QOUT_ELEMS  (BN * DIM)               // 8388608
#define IDX_OFF     QOUT_ELEMS
#define IDX_ELEMS   (BN * NQ)                // 65536
#define LOSS_OFF    (IDX_OFF + IDX_ELEMS)
#define OUT_FULL    (LOSS_OFF + NQ)

typedef unsigned long long ull;

// ---------------- device scratch (static globals; no runtime alloc) ----------
__device__ float  g_cbn[(size_t)NQ * CBSZ];     // normalized implicit codebooks (32MB)
__device__ float  g_xn [(size_t)BN * DIM];      // l2norm(residual) (32MB)
__device__ float  g_res[(size_t)BN * DIM];      // residual (32MB)
__device__ int    g_idx[BN];
__device__ double g_loss[NQ];

// ---------------- f32x2 helpers (Blackwell packed fp32) ----------------------
__device__ __forceinline__ ull dup2(float x) {
    ull r; asm("mov.b64 %0, {%1, %1};" : "=l"(r) : "f"(x)); return r;
}
__device__ __forceinline__ void fma2(ull& a, ull x, ull y) {
    asm("fma.rn.f32x2 %0, %1, %2, %0;" : "+l"(a) : "l"(x), "l"(y));
}
__device__ __forceinline__ float lo2(ull a) { return __uint_as_float((unsigned)a); }
__device__ __forceinline__ float hi2(ull a) { return __uint_as_float((unsigned)(a >> 32)); }

__device__ __forceinline__ float warp_sum(float v) {
    #pragma unroll
    for (int o = 16; o; o >>= 1) v += __shfl_xor_sync(0xffffffffu, v, o);
    return v;
}

// ---------------- misc small kernels -----------------------------------------
__global__ void zero_loss_kernel() {
    if (threadIdx.x < NQ) g_loss[threadIdx.x] = 0.0;
}

__global__ void finalize_loss_kernel(float* out) {
    if (threadIdx.x < NQ)
        out[LOSS_OFF + threadIdx.x] =
            (float)(g_loss[threadIdx.x] * 1.25 / (double)QOUT_ELEMS);
}

// residual = x ; x_n = x / max(||x||, 1e-12)   (one block per token row)
__global__ void init_xr_kernel(const float* __restrict__ x) {
    int row = blockIdx.x;
    int t   = threadIdx.x;                  // 128 threads, 1 float4 each
    const float4* xr = (const float4*)(x + (size_t)row * DIM);
    float4 v = xr[t];
    float s = v.x * v.x + v.y * v.y + v.z * v.z + v.w * v.w;
    s = warp_sum(s);
    __shared__ float ps[4];
    if ((t & 31) == 0) ps[t >> 5] = s;
    __syncthreads();
    float tot = ps[0] + ps[1] + ps[2] + ps[3];
    float inv = 1.0f / fmaxf(sqrtf(tot), 1e-12f);
    ((float4*)(g_res + (size_t)row * DIM))[t] = v;
    float4 n = make_float4(v.x * inv, v.y * inv, v.z * inv, v.w * inv);
    ((float4*)(g_xn + (size_t)row * DIM))[t] = n;
}

// in-place row l2norm of g_cbn (one block per row; NQ*NC rows)
__global__ void cb_norm_kernel() {
    size_t row = blockIdx.x;
    int t = threadIdx.x;
    float4* r = (float4*)(g_cbn + row * DIM);
    float4 v = r[t];
    float s = v.x * v.x + v.y * v.y + v.z * v.z + v.w * v.w;
    s = warp_sum(s);
    __shared__ float ps[4];
    if ((t & 31) == 0) ps[t >> 5] = s;
    __syncthreads();
    float tot = ps[0] + ps[1] + ps[2] + ps[3];
    float inv = 1.0f / fmaxf(sqrtf(tot), 1e-12f);
    r[t] = make_float4(v.x * inv, v.y * inv, v.z * inv, v.w * inv);
}

// ---------------- implicit codebook GEMM --------------------------------------
// cb_raw[s][c][d] = sum_k codebooks[s][c][k] * weights[s][d][k]
// Tile: 64 c-rows x 128 d-cols, 128 threads (16 cols x 8 rows), micro 8x8 via f32x2.
__global__ void __launch_bounds__(128)
cb_gemm_kernel(const float* __restrict__ codebooks, const float* __restrict__ weights) {
    __shared__ __align__(16) float xs[16][64];   // codebook rows, k-major transposed
    __shared__ __align__(16) float cs[16][128];  // weight rows

    int tid = threadIdx.x;
    int row = tid & 7;        // token-group (c dimension)
    int col = tid >> 3;       // code-group (d dimension), 0..15

    int stage = blockIdx.z;
    int m0 = blockIdx.x * 64;     // c base
    int n0 = blockIdx.y * 128;    // d base
    const float* A = codebooks + (size_t)stage * NC * DIM;
    const float* Bm = weights  + (size_t)stage * DIM * DIM;

    ull acc[4][8];
    #pragma unroll
    for (int p = 0; p < 4; p++)
        #pragma unroll
        for (int c = 0; c < 8; c++) acc[p][c] = 0ull;

    for (int kc = 0; kc < 32; kc++) {
        int k0 = kc * 16;
        __syncthreads();
        #pragma unroll
        for (int i = 0; i < 2; i++) {
            int item = tid * 2 + i;
            int tok = item >> 2, k4 = item & 3;
            float4 v = *(const float4*)(A + (size_t)(m0 + tok) * DIM + k0 + k4 * 4);
            xs[k4 * 4 + 0][tok] = v.x; xs[k4 * 4 + 1][tok] = v.y;
            xs[k4 * 4 + 2][tok] = v.z; xs[k4 * 4 + 3][tok] = v.w;
        }
        #pragma unroll
        for (int j = 0; j < 4; j++) {
            int item = j * 128 + tid;
            int code = item >> 2, k4 = item & 3;
            float4 v = *(const float4*)(Bm + (size_t)(n0 + code) * DIM + k0 + k4 * 4);
            cs[k4 * 4 + 0][code] = v.x; cs[k4 * 4 + 1][code] = v.y;
            cs[k4 * 4 + 2][code] = v.z; cs[k4 * 4 + 3][code] = v.w;
        }
        __syncthreads();
        #pragma unroll
        for (int kk = 0; kk < 16; kk++) {
            ull a[4];
            #pragma unroll
            for (int p = 0; p < 4; p++)
                a[p] = *(const ull*)&xs[kk][row * 8 + 2 * p];
            ull b[8];
            #pragma unroll
            for (int c = 0; c < 8; c++) b[c] = dup2(cs[kk][col * 8 + c]);
            #pragma unroll
            for (int p = 0; p < 4; p++)
                #pragma unroll
                for (int c = 0; c < 8; c++) fma2(acc[p][c], a[p], b[c]);
        }
    }

    float* out = g_cbn + (size_t)stage * CBSZ;
    #pragma unroll
    for (int p = 0; p < 4; p++) {
        int cg = m0 + row * 8 + 2 * p;
        #pragma unroll
        for (int c = 0; c < 8; c++) {
            int d = n0 + col * 8 + c;
            out[(size_t)cg * DIM + d]       = lo2(acc[p][c]);
            out[(size_t)(cg + 1) * DIM + d] = hi2(acc[p][c]);
        }
    }
}

// ---------------- fused similarity GEMM + argmax -------------------------------
// For 64 tokens per block, scan all 4096 codes in 128-wide tiles, keep running best.
__global__ void __launch_bounds__(128)
sim_argmax_kernel(int stage) {
    __shared__ __align__(16) float xs[16][64];
    __shared__ __align__(16) float cs[16][128];
    __shared__ float sval[64][17];
    __shared__ int   sidx[64][17];

    int tid = threadIdx.x;
    int row = tid & 7;
    int col = tid >> 3;
    int m0 = blockIdx.x * 64;
    const float* xn = g_xn;
    const float* cb = g_cbn + (size_t)stage * CBSZ;

    float best[8]; int bidx[8];
    #pragma unroll
    for (int i = 0; i < 8; i++) { best[i] = -1e30f; bidx[i] = 0; }

    for (int tile = 0; tile < NC / 128; tile++) {
        int c0 = tile * 128;
        ull acc[4][8];
        #pragma unroll
        for (int p = 0; p < 4; p++)
            #pragma unroll
            for (int c = 0; c < 8; c++) acc[p][c] = 0ull;

        for (int kc = 0; kc < 32; kc++) {
            int k0 = kc * 16;
            __syncthreads();
            #pragma unroll
            for (int i = 0; i < 2; i++) {
                int item = tid * 2 + i;
                int tok = item >> 2, k4 = item & 3;
                float4 v = *(const float4*)(xn + (size_t)(m0 + tok) * DIM + k0 + k4 * 4);
                xs[k4 * 4 + 0][tok] = v.x; xs[k4 * 4 + 1][tok] = v.y;
                xs[k4 * 4 + 2][tok] = v.z; xs[k4 * 4 + 3][tok] = v.w;
            }
            #pragma unroll
            for (int j = 0; j < 4; j++) {
                int item = j * 128 + tid;
                int code = item >> 2, k4 = item & 3;
                float4 v = *(const float4*)(cb + (size_t)(c0 + code) * DIM + k0 + k4 * 4);
                cs[k4 * 4 + 0][code] = v.x; cs[k4 * 4 + 1][code] = v.y;
                cs[k4 * 4 + 2][code] = v.z; cs[k4 * 4 + 3][code] = v.w;
            }
            __syncthreads();
            #pragma unroll
            for (int kk = 0; kk < 16; kk++) {
                ull a[4];
                #pragma unroll
                for (int p = 0; p < 4; p++)
                    a[p] = *(const ull*)&xs[kk][row * 8 + 2 * p];
                ull b[8];
                #pragma unroll
                for (int c = 0; c < 8; c++) b[c] = dup2(cs[kk][col * 8 + c]);
                #pragma unroll
                for (int p = 0; p < 4; p++)
                    #pragma unroll
                    for (int c = 0; c < 8; c++) fma2(acc[p][c], a[p], b[c]);
            }
        }
        // update running argmax (codes ascending within thread)
        #pragma unroll
        for (int p = 0; p < 4; p++)
            #pragma unroll
            for (int c = 0; c < 8; c++) {
                int code = c0 + col * 8 + c;
                float s0 = lo2(acc[p][c]);
                float s1 = hi2(acc[p][c]);
                if (s0 > best[2 * p])     { best[2 * p] = s0;     bidx[2 * p] = code; }
                if (s1 > best[2 * p + 1]) { best[2 * p + 1] = s1; bidx[2 * p + 1] = code; }
            }
    }

    __syncthreads();
    #pragma unroll
    for (int lt = 0; lt < 8; lt++) {
        sval[row * 8 + lt][col] = best[lt];
        sidx[row * 8 + lt][col] = bidx[lt];
    }
    __syncthreads();
    if (tid < 64) {
        float bv = -1e30f; int bi = NC;
        #pragma unroll
        for (int c = 0; c < 16; c++) {
            float v = sval[tid][c]; int i = sidx[tid][c];
            if (v > bv || (v == bv && i < bi)) { bv = v; bi = i; }
        }
        g_idx[m0 + tid] = bi;
    }
}

// ---------------- rotation-trick update per token ------------------------------
// out = ax*x_n + aq*quant ; residual -= out ; quantized_out += out ; next x_n.
__global__ void rotate_update_kernel(int stage, float* __restrict__ out, int write_aux) {
    int warp = threadIdx.x >> 5;
    int lane = threadIdx.x & 31;
    int token = blockIdx.x * 8 + warp;

    const float4* xr = (const float4*)(g_xn + (size_t)token * DIM);
    float4*       rr = (float4*)(g_res + (size_t)token * DIM);
    int code = g_idx[token];
    const float4* qr = (const float4*)(g_cbn + (size_t)stage * CBSZ + (size_t)code * DIM);

    float4 xv[4], qv[4];
    float see = 0.f, stt = 0.f, set = 0.f;
    #pragma unroll
    for (int j = 0; j < 4; j++) {
        xv[j] = xr[lane + j * 32];
        qv[j] = qr[lane + j * 32];
        see += xv[j].x * xv[j].x + xv[j].y * xv[j].y + xv[j].z * xv[j].z + xv[j].w * xv[j].w;
        stt += qv[j].x * qv[j].x + qv[j].y * qv[j].y + qv[j].z * qv[j].z + qv[j].w * qv[j].w;
        set += xv[j].x * qv[j].x + xv[j].y * qv[j].y + xv[j].z * qv[j].z + xv[j].w * qv[j].w;
    }
    see = warp_sum(see); stt = warp_sum(stt); set = warp_sum(set);

    float ns = sqrtf(see), nt = sqrtf(stt);
    float eu = see / ns;
    float eq = set / nt;
    float nw2 = 2.f + 2.f * set / (ns * nt);
    float nw = fmaxf(sqrtf(nw2), 1e-12f);
    float cw = 2.f * (eu + eq) / (nw * nw);
    float ax = (nt / ns) * (1.f - cw / ns);
    float aq = (2.f * eu - cw) / ns;
    float scc = see - 2.f * set + stt;       // sum((x_n - quant)^2)

    float4* qo = (float4*)(out + (size_t)token * DIM);
    float rn2 = 0.f;
    float4 rnv[4];
    #pragma unroll
    for (int j = 0; j < 4; j++) {
        float4 o;
        o.x = ax * xv[j].x + aq * qv[j].x;
        o.y = ax * xv[j].y + aq * qv[j].y;
        o.z = ax * xv[j].z + aq * qv[j].z;
        o.w = ax * xv[j].w + aq * qv[j].w;
        float4 r = rr[lane + j * 32];
        if (stage == 0) {
            qo[lane + j * 32] = o;
        } else {
            float4 prev = qo[lane + j * 32];
            prev.x += o.x; prev.y += o.y; prev.z += o.z; prev.w += o.w;
            qo[lane + j * 32] = prev;
        }
        float4 rn;
        rn.x = r.x - o.x; rn.y = r.y - o.y; rn.z = r.z - o.z; rn.w = r.w - o.w;
        rr[lane + j * 32] = rn;
        rnv[j] = rn;
        rn2 += rn.x * rn.x + rn.y * rn.y + rn.z * rn.z + rn.w * rn.w;
    }
    if (stage < NQ - 1) {
        rn2 = warp_sum(rn2);
        float inv = 1.f / fmaxf(sqrtf(rn2), 1e-12f);
        float4* xw = (float4*)(g_xn + (size_t)token * DIM);
        #pragma unroll
        for (int j = 0; j < 4; j++) {
            float4 n = make_float4(rnv[j].x * inv, rnv[j].y * inv,
                                   rnv[j].z * inv, rnv[j].w * inv);
            xw[lane + j * 32] = n;
        }
    }
    if (lane == 0 && write_aux)
        out[IDX_OFF + (size_t)token * NQ + stage] = (float)code;

    // loss accumulation (block-level, then one double atomic)
    __shared__ float wscc[8];
    if (lane == 0) wscc[warp] = scc;
    __syncthreads();
    if (threadIdx.x == 0) {
        float s = 0.f;
        #pragma unroll
        for (int w = 0; w < 8; w++) s += wscc[w];
        atomicAdd(&g_loss[stage], (double)s);
    }
}

// ---------------- launch ------------------------------------------------------
extern "C" void kernel_launch(void* const* d_in, const int* in_sizes, int n_in,
                              void* d_out, int out_size) {
    const float* x         = (const float*)d_in[0];
    const float* codebooks = (const float*)d_in[1];
    const float* weights   = (const float*)d_in[2];
    float* out = (float*)d_out;
    int write_aux = (out_size >= OUT_FULL) ? 1 : 0;

    zero_loss_kernel<<<1, 32>>>();
    cb_gemm_kernel<<<dim3(NC / 64, DIM / 128, NQ), 128>>>(codebooks, weights);
    cb_norm_kernel<<<NQ * NC, 128>>>();
    init_xr_kernel<<<BN, 128>>>(x);
    for (int s = 0; s < NQ; s++) {
        sim_argmax_kernel<<<BN / 64, 128>>>(s);
        rotate_update_kernel<<<BN / 8, 256>>>(s, out, write_aux);
    }
    if (write_aux) finalize_loss_kernel<<<1, 32>>>(out);
}